// round 2
// baseline (speedup 1.0000x reference)
#include <cuda_runtime.h>
#include <math.h>

#define HH 16
#define SS 4096
#define DD 64
#define SCALE 0.125f

static __device__ __forceinline__ float neg_inf() {
    return __int_as_float(0xff800000);
}

// ---------------------------------------------------------------------------
// K1: scores[h][q][k] = mask ? -inf : (Q . K) * scale
// Block tile: 128 q-rows x 64 k-cols. 256 threads, 8x4 micro-tile per thread.
// smem: Qs[d][qrow] (64x128), Ks[d][kcol] (64x64)  -> exactly 48KB
// ---------------------------------------------------------------------------
__global__ __launch_bounds__(256) void scores_kernel(
    const float* __restrict__ q, const float* __restrict__ k,
    const int* __restrict__ mask, float* __restrict__ attn)
{
    __shared__ float Qs[DD][128];
    __shared__ float Ks[DD][64];

    const int h  = blockIdx.z;
    const int q0 = blockIdx.y * 128;
    const int k0 = blockIdx.x * 64;
    const int tid = threadIdx.x;

    const float* qb = q + ((size_t)h * SS + q0) * DD;
    const float* kb = k + ((size_t)h * SS + k0) * DD;

    // Load Q tile (128 rows x 64 d), transposed into Qs[d][row]
#pragma unroll
    for (int i = 0; i < 8; i++) {
        int linear = tid + i * 256;        // 0..2047
        int row = linear >> 4;             // 16 float4 per row
        int dg  = (linear & 15) * 4;
        float4 t = *(const float4*)(qb + (size_t)row * DD + dg);
        Qs[dg + 0][row] = t.x; Qs[dg + 1][row] = t.y;
        Qs[dg + 2][row] = t.z; Qs[dg + 3][row] = t.w;
    }
    // Load K tile (64 rows x 64 d), transposed into Ks[d][col]
#pragma unroll
    for (int i = 0; i < 4; i++) {
        int linear = tid + i * 256;        // 0..1023
        int row = linear >> 4;
        int dg  = (linear & 15) * 4;
        float4 t = *(const float4*)(kb + (size_t)row * DD + dg);
        Ks[dg + 0][row] = t.x; Ks[dg + 1][row] = t.y;
        Ks[dg + 2][row] = t.z; Ks[dg + 3][row] = t.w;
    }
    __syncthreads();

    const int tx = tid & 15;   // col group: cols tx*4 .. tx*4+3
    const int ty = tid >> 4;   // row group: rows ty*4..+3 and 64+ty*4..+3

    float acc[8][4];
#pragma unroll
    for (int r = 0; r < 8; r++)
#pragma unroll
        for (int c = 0; c < 4; c++) acc[r][c] = 0.f;

#pragma unroll 8
    for (int d = 0; d < DD; d++) {
        float4 a0 = *(float4*)&Qs[d][ty * 4];
        float4 a1 = *(float4*)&Qs[d][64 + ty * 4];
        float4 b  = *(float4*)&Ks[d][tx * 4];
        float av[8] = {a0.x, a0.y, a0.z, a0.w, a1.x, a1.y, a1.z, a1.w};
        float bv[4] = {b.x, b.y, b.z, b.w};
#pragma unroll
        for (int r = 0; r < 8; r++)
#pragma unroll
            for (int c = 0; c < 4; c++) acc[r][c] += av[r] * bv[c];
    }

    // Epilogue: scale, mask (int32 per element!), write
    const int colg0 = k0 + tx * 4;
#pragma unroll
    for (int r = 0; r < 8; r++) {
        int rowl = (r < 4) ? (ty * 4 + r) : (64 + ty * 4 + (r - 4));
        int rowg = q0 + rowl;
        int4 mv = *(const int4*)(mask + (size_t)rowg * SS + colg0);
        float4 o;
        o.x = mv.x ? neg_inf() : acc[r][0] * SCALE;
        o.y = mv.y ? neg_inf() : acc[r][1] * SCALE;
        o.z = mv.z ? neg_inf() : acc[r][2] * SCALE;
        o.w = mv.w ? neg_inf() : acc[r][3] * SCALE;
        *(float4*)(attn + ((size_t)h * SS + rowg) * SS + colg0) = o;
    }
}

// ---------------------------------------------------------------------------
// K2: in-place row softmax on attn. One block (256 thr) per row of 4096.
// ---------------------------------------------------------------------------
__global__ __launch_bounds__(256) void softmax_kernel(float* __restrict__ attn)
{
    const int b = blockIdx.x;
    const int h = b >> 12;
    const int row = b & 4095;
    float* p = attn + ((size_t)h * SS + row) * SS;
    const int tid = threadIdx.x;
    const int lane = tid & 31, warp = tid >> 5;

    __shared__ float sred[8];
    __shared__ float bcast;

    float4 v[4];
    float m = neg_inf();
#pragma unroll
    for (int i = 0; i < 4; i++) {
        v[i] = ((const float4*)p)[tid + i * 256];
        m = fmaxf(m, fmaxf(fmaxf(v[i].x, v[i].y), fmaxf(v[i].z, v[i].w)));
    }
#pragma unroll
    for (int o = 16; o > 0; o >>= 1)
        m = fmaxf(m, __shfl_xor_sync(0xffffffffu, m, o));
    if (lane == 0) sred[warp] = m;
    __syncthreads();
    if (tid == 0) {
        float t = sred[0];
#pragma unroll
        for (int i = 1; i < 8; i++) t = fmaxf(t, sred[i]);
        bcast = t;
    }
    __syncthreads();
    m = bcast;

    float sum = 0.f;
#pragma unroll
    for (int i = 0; i < 4; i++) {
        v[i].x = __expf(v[i].x - m);
        v[i].y = __expf(v[i].y - m);
        v[i].z = __expf(v[i].z - m);
        v[i].w = __expf(v[i].w - m);
        sum += (v[i].x + v[i].y) + (v[i].z + v[i].w);
    }
#pragma unroll
    for (int o = 16; o > 0; o >>= 1)
        sum += __shfl_xor_sync(0xffffffffu, sum, o);
    __syncthreads();   // protect sred reuse
    if (lane == 0) sred[warp] = sum;
    __syncthreads();
    if (tid == 0) {
        float t = 0.f;
#pragma unroll
        for (int i = 0; i < 8; i++) t += sred[i];
        bcast = t;
    }
    __syncthreads();
    const float inv = 1.0f / bcast;

#pragma unroll
    for (int i = 0; i < 4; i++) {
        v[i].x *= inv; v[i].y *= inv; v[i].z *= inv; v[i].w *= inv;
        ((float4*)p)[tid + i * 256] = v[i];
    }
}

// ---------------------------------------------------------------------------
// K3: out[h][q][d] = sum_k attn[h][q][k] * v[h][k][d]
// Block tile: 128 q-rows x 64 d-cols, k-chunks of 64.
// smem: As[k][row] (64x128), Vs[k][d] (64x64)  -> 48KB
// ---------------------------------------------------------------------------
__global__ __launch_bounds__(256) void pv_kernel(
    const float* __restrict__ attn, const float* __restrict__ v,
    float* __restrict__ out)
{
    __shared__ float As[64][128];
    __shared__ float Vs[64][DD];

    const int h  = blockIdx.z;
    const int q0 = blockIdx.y * 128;
    const int tid = threadIdx.x;
    const int tx = tid & 15;
    const int ty = tid >> 4;

    const float* ab = attn + ((size_t)h * SS + q0) * SS;
    const float* vb = v + (size_t)h * SS * DD;

    float acc[8][4];
#pragma unroll
    for (int r = 0; r < 8; r++)
#pragma unroll
        for (int c = 0; c < 4; c++) acc[r][c] = 0.f;

    for (int kc = 0; kc < SS; kc += 64) {
        // attn tile: 128 rows x 64 k, transposed into As[k][row]
#pragma unroll
        for (int i = 0; i < 8; i++) {
            int linear = tid + i * 256;
            int row = linear >> 4;
            int kg  = (linear & 15) * 4;
            float4 t = *(const float4*)(ab + (size_t)row * SS + kc + kg);
            As[kg + 0][row] = t.x; As[kg + 1][row] = t.y;
            As[kg + 2][row] = t.z; As[kg + 3][row] = t.w;
        }
        // V tile: 64 k x 64 d, natural layout
#pragma unroll
        for (int i = 0; i < 4; i++) {
            int linear = tid + i * 256;
            int kr = linear >> 4;
            int dg = (linear & 15) * 4;
            *(float4*)&Vs[kr][dg] =
                *(const float4*)(vb + (size_t)(kc + kr) * DD + dg);
        }
        __syncthreads();

#pragma unroll 8
        for (int kk = 0; kk < 64; kk++) {
            float4 a0 = *(float4*)&As[kk][ty * 4];
            float4 a1 = *(float4*)&As[kk][64 + ty * 4];
            float4 b  = *(float4*)&Vs[kk][tx * 4];
            float av[8] = {a0.x, a0.y, a0.z, a0.w, a1.x, a1.y, a1.z, a1.w};
            float bv[4] = {b.x, b.y, b.z, b.w};
#pragma unroll
            for (int r = 0; r < 8; r++)
#pragma unroll
                for (int c = 0; c < 4; c++) acc[r][c] += av[r] * bv[c];
        }
        __syncthreads();
    }

#pragma unroll
    for (int r = 0; r < 8; r++) {
        int rowl = (r < 4) ? (ty * 4 + r) : (64 + ty * 4 + (r - 4));
        int rowg = q0 + rowl;
        float4 o = make_float4(acc[r][0], acc[r][1], acc[r][2], acc[r][3]);
        *(float4*)(out + ((size_t)h * SS + rowg) * DD + tx * 4) = o;
    }
}

// ---------------------------------------------------------------------------
extern "C" void kernel_launch(void* const* d_in, const int* in_sizes, int n_in,
                              void* d_out, int out_size)
{
    const float* q = (const float*)d_in[0];
    const float* k = (const float*)d_in[1];
    const float* v = (const float*)d_in[2];
    const int* mask = (const int*)d_in[3];

    float* out  = (float*)d_out;                         // [16,4096,64]
    float* attn = out + (size_t)HH * SS * DD;            // [16,4096,4096]

    dim3 g1(SS / 64, SS / 128, HH);
    scores_kernel<<<g1, 256>>>(q, k, mask, attn);

    softmax_kernel<<<HH * SS, 256>>>(attn);

    dim3 g3(1, SS / 128, HH);
    pv_kernel<<<g3, 256>>>(attn, v, out);
}